// round 16
// baseline (speedup 1.0000x reference)
#include <cuda_runtime.h>

// RoIPooling2D (Caffe roi_pool, max) — FUSED single kernel:
//   Phase A: NCHW -> NHWC transpose (tiles strided over all blocks) + bounds
//   device-wide epoch barrier (all 256 blocks co-resident: lb(512,2) -> 296 slots)
//   Phase B: NHWC gather, exact-window batched loads (R15, proven 10.2us)
// Bounds replicate XLA:GPU arithmetic exactly (div.full.f32, proven Round 3).
// Barrier is monotonic (no reset) -> safe across graph replays.

#define POOL_H 7
#define POOL_W 7
#define NBINS  (POOL_H * POOL_W)       // 49
#define SPATIAL_SCALE 0.0625f
#define C_TOT  256
#define HDIM   50
#define WDIM   50
#define HW     (HDIM * WDIM)           // 2500
#define CH     128                     // channels per gather block (half)
#define NUNITS (NBINS * 2)             // 98: (bin, 64-ch sub-half)
#define GTHREADS 512
#define NWARPS (GTHREADS / 32)
#define ROWSTRIDE (WDIM * C_TOT)
#define PTILES ((HW + 31) / 32)        // 79
#define NEG_FLT_MAX (-3.402823466e38f)

__device__ float g_xt[2 * HW * C_TOT];          // NHWC scratch, 5.12 MB
__device__ unsigned int g_cnt = 0;              // monotonic arrivals
__device__ volatile unsigned int g_rel = 0;     // monotonic released epoch

__device__ __forceinline__ float div_full(float a, float b) {
    float r;
    asm("div.full.f32 %0, %1, %2;" : "=f"(r) : "f"(a), "f"(b));
    return r;
}

__device__ __forceinline__ float2 ld2(const float* p) {
    return __ldg(reinterpret_cast<const float2*>(p));
}
__device__ __forceinline__ void mx(float2& m, float2 v) {
    m.x = fmaxf(m.x, v.x);
    m.y = fmaxf(m.y, v.y);
}

// Straight-line gather of exactly WH x WW float2 loads (one exposure).
template <int WH, int WW>
__device__ __forceinline__ float2 gather_unit(const float* base) {
    float2 r[WH][WW];
    #pragma unroll
    for (int h = 0; h < WH; ++h) {
        const float* rp = base + h * ROWSTRIDE;
        #pragma unroll
        for (int w = 0; w < WW; ++w)
            r[h][w] = ld2(rp + w * C_TOT);
    }
    #pragma unroll
    for (int h = 0; h < WH; ++h) {
        #pragma unroll
        for (int w = 1; w < WW; ++w)
            mx(r[h][0], r[h][w]);
    }
    #pragma unroll
    for (int h = 1; h < WH; ++h)
        mx(r[0][0], r[h][0]);
    return r[0][0];
}

__global__ void __launch_bounds__(GTHREADS, 2)
roi_fused_kernel(const float* __restrict__ x, const float* __restrict__ rois,
                 float* __restrict__ out, int N, int B) {
    // s_res doubles as the transpose tile buffer in Phase A (4.3 KB of 25 KB).
    __shared__ float s_res[CH * NBINS];
    __shared__ int   s_hs[POOL_H], s_he[POOL_H], s_ws[POOL_W], s_we[POOL_W];
    __shared__ int   s_b;

    int n    = blockIdx.x;
    int half = blockIdx.y;
    int tid  = threadIdx.x;
    int warp = tid >> 5;
    int lane = tid & 31;
    int nblk = gridDim.x * gridDim.y;           // 256
    int bid  = blockIdx.y * gridDim.x + blockIdx.x;

    // --- bounds (exact replica of reference arithmetic, incl. div.full) ---
    if (tid < POOL_H + POOL_W + 1) {
        const float* r = rois + n * 5;
        if (tid == POOL_H + POOL_W) {
            s_b = (int)r[0];
        } else {
            bool is_h = (tid < POOL_H);
            int  i    = is_h ? tid : tid - POOL_H;
            float s1  = rintf(__fmul_rn(r[is_h ? 2 : 1], SPATIAL_SCALE));
            float e1  = rintf(__fmul_rn(r[is_h ? 4 : 3], SPATIAL_SCALE));
            float sz  = fmaxf(__fadd_rn(__fsub_rn(e1, s1), 1.0f), 1.0f);
            float bs  = div_full(sz, is_h ? (float)POOL_H : (float)POOL_W);
            float npx = is_h ? (float)HDIM : (float)WDIM;
            float lo = __fadd_rn(floorf(__fmul_rn((float)i, bs)), s1);
            float hi = __fadd_rn(ceilf(__fmul_rn((float)(i + 1), bs)), s1);
            lo = fminf(fmaxf(lo, 0.0f), npx);
            hi = fminf(fmaxf(hi, 0.0f), npx);
            if (is_h) { s_hs[i] = (int)lo; s_he[i] = (int)hi; }
            else      { s_ws[i] = (int)lo; s_we[i] = (int)hi; }
        }
    }

    // --- Phase A: NCHW -> NHWC transpose, tiles strided over all blocks ---
    {
        float* tile = s_res;                     // 32 x 33 floats
        int tx = lane;
        int ty = warp;                           // 0..15
        int ntiles = B * (C_TOT / 32) * PTILES;  // 2*8*79 = 1264
        for (int t = bid; t < ntiles; t += nblk) {
            int b   = t / ((C_TOT / 32) * PTILES);
            int rem = t - b * ((C_TOT / 32) * PTILES);
            int c0  = (rem / PTILES) * 32;
            int p0  = (rem - (rem / PTILES) * PTILES) * 32;

            __syncthreads();                     // tile buffer reuse guard
            #pragma unroll
            for (int k = 0; k < 2; ++k) {
                int c = c0 + ty + k * 16;
                int p = p0 + tx;
                if (p < HW)
                    tile[(ty + k * 16) * 33 + tx] =
                        x[((size_t)b * C_TOT + c) * HW + p];
            }
            __syncthreads();
            #pragma unroll
            for (int k = 0; k < 2; ++k) {
                int p = p0 + ty + k * 16;
                int c = c0 + tx;
                if (p < HW)
                    g_xt[((size_t)b * HW + p) * C_TOT + c] =
                        tile[tx * 33 + ty + k * 16];
            }
        }
    }

    // --- device-wide epoch barrier (monotonic, replay-safe) ---
    __threadfence();
    __syncthreads();
    if (tid == 0) {
        unsigned int t = atomicAdd(&g_cnt, 1u);
        unsigned int epoch = t / (unsigned)nblk + 1u;
        if ((t % (unsigned)nblk) == (unsigned)nblk - 1u) {
            g_rel = epoch;                       // release (volatile store)
            __threadfence();
        } else {
            while (g_rel < epoch) { }            // spin (volatile load)
        }
    }
    __syncthreads();
    __threadfence();

    // --- Phase B: gather. unit = (bin, 64-ch sub); lane = 2 ch (float2) ---
    const float* xroi = g_xt + (size_t)s_b * (HW * C_TOT) + half * CH;

    // Contiguous unit range per warp (adjacent bins -> L1 locality).
    int u0 = (warp * NUNITS) / NWARPS;
    int u1 = ((warp + 1) * NUNITS) / NWARPS;

    for (int u = u0; u < u1; ++u) {
        int bin = u >> 1;
        int sub = u & 1;
        int ph  = bin / POOL_W;
        int pw  = bin - ph * POOL_W;
        int hs = s_hs[ph], he = s_he[ph];
        int ws = s_ws[pw], we = s_we[pw];
        int wh = he - hs, ww = we - ws;

        float2 m;
        if (wh > 0 && ww > 0 && wh <= 4 && ww <= 4) {
            const float* base = xroi + ((size_t)(hs * WDIM) + ws) * C_TOT
                                     + sub * 64 + lane * 2;
            switch (((wh - 1) << 2) | (ww - 1)) {
                case  0: m = gather_unit<1,1>(base); break;
                case  1: m = gather_unit<1,2>(base); break;
                case  2: m = gather_unit<1,3>(base); break;
                case  3: m = gather_unit<1,4>(base); break;
                case  4: m = gather_unit<2,1>(base); break;
                case  5: m = gather_unit<2,2>(base); break;
                case  6: m = gather_unit<2,3>(base); break;
                case  7: m = gather_unit<2,4>(base); break;
                case  8: m = gather_unit<3,1>(base); break;
                case  9: m = gather_unit<3,2>(base); break;
                case 10: m = gather_unit<3,3>(base); break;
                case 11: m = gather_unit<3,4>(base); break;
                case 12: m = gather_unit<4,1>(base); break;
                case 13: m = gather_unit<4,2>(base); break;
                case 14: m = gather_unit<4,3>(base); break;
                default: m = gather_unit<4,4>(base); break;
            }
        } else if (wh > 0 && ww > 0) {
            // Fallback (never hit with this data shape, kept for safety).
            m = make_float2(NEG_FLT_MAX, NEG_FLT_MAX);
            const float* rowp = xroi + ((size_t)(hs * WDIM) + ws) * C_TOT
                                     + sub * 64 + lane * 2;
            for (int h = 0; h < wh; ++h) {
                const float* q = rowp;
                for (int w = 0; w < ww; ++w) { mx(m, ld2(q)); q += C_TOT; }
                rowp += ROWSTRIDE;
            }
        } else {
            m = make_float2(0.f, 0.f);
        }

        int c = sub * 64 + lane * 2;
        s_res[(c + 0) * NBINS + bin] = m.x;
        s_res[(c + 1) * NBINS + bin] = m.y;
    }
    __syncthreads();

    // --- coalesced staged write: flat 6272 floats = 1568 float4 ---
    float* obase = out + (size_t)n * (C_TOT * NBINS) + (size_t)half * (CH * NBINS);
    const float4* src = reinterpret_cast<const float4*>(s_res);
    float4* dst = reinterpret_cast<float4*>(obase);
    #pragma unroll
    for (int k = 0; k < (CH * NBINS) / 4 / GTHREADS + 1; ++k) {
        int i = tid + k * GTHREADS;
        if (i < (CH * NBINS) / 4)
            dst[i] = src[i];
    }
}

extern "C" void kernel_launch(void* const* d_in, const int* in_sizes, int n_in,
                              void* d_out, int out_size) {
    const float* x    = (const float*)d_in[0];   // [B,256,50,50]
    const float* rois = (const float*)d_in[1];   // [N,5]
    float* out = (float*)d_out;                  // [N,256,7,7]

    const int N = in_sizes[1] / 5;
    const int B = in_sizes[0] / (C_TOT * HW);

    dim3 grid(N, C_TOT / CH);                    // (128, 2) = 256 blocks
    roi_fused_kernel<<<grid, GTHREADS>>>(x, rois, out, N, B);
}

// round 17
// speedup vs baseline: 1.1996x; 1.1996x over previous
#include <cuda_runtime.h>

// RoIPooling2D (Caffe roi_pool, max) — NHWC gather, exact-window loads,
// channel-quartered blocks (halved per-warp serial depth vs R15).
// x [B=2,C=256,H=50,W=50] f32, rois [N,5], out [N,256,7,7] f32.
// Bounds replicate XLA:GPU arithmetic exactly (div.full.f32, proven Round 3).
//
//   1) transpose_in: NCHW -> g_xt NHWC (proven ~2.4us)
//   2) gather: grid (N, 4 ch-quarters) = 512 blocks, 512 thr (16 warps).
//      unit = bin (lane = 2 channels x 32 = 64 ch/block): 49 units ->
//      ~3 dependent exposure rounds per warp (vs 6 in R15).

#define POOL_H 7
#define POOL_W 7
#define NBINS  (POOL_H * POOL_W)       // 49
#define SPATIAL_SCALE 0.0625f
#define C_TOT  256
#define HDIM   50
#define WDIM   50
#define HW     (HDIM * WDIM)
#define CQ     64                      // channels per gather block (quarter)
#define GTHREADS 512
#define NWARPS (GTHREADS / 32)
#define ROWSTRIDE (WDIM * C_TOT)
#define NEG_FLT_MAX (-3.402823466e38f)

__device__ float g_xt[2 * HW * C_TOT];  // NHWC scratch, 5.12 MB

__device__ __forceinline__ float div_full(float a, float b) {
    float r;
    asm("div.full.f32 %0, %1, %2;" : "=f"(r) : "f"(a), "f"(b));
    return r;
}

__device__ __forceinline__ float2 ld2(const float* p) {
    return __ldg(reinterpret_cast<const float2*>(p));
}
__device__ __forceinline__ void mx(float2& m, float2 v) {
    m.x = fmaxf(m.x, v.x);
    m.y = fmaxf(m.y, v.y);
}

// Straight-line gather of exactly WH x WW float2 loads (one exposure).
template <int WH, int WW>
__device__ __forceinline__ float2 gather_unit(const float* base) {
    float2 r[WH][WW];
    #pragma unroll
    for (int h = 0; h < WH; ++h) {
        const float* rp = base + h * ROWSTRIDE;
        #pragma unroll
        for (int w = 0; w < WW; ++w)
            r[h][w] = ld2(rp + w * C_TOT);
    }
    #pragma unroll
    for (int h = 0; h < WH; ++h) {
        #pragma unroll
        for (int w = 1; w < WW; ++w)
            mx(r[h][0], r[h][w]);
    }
    #pragma unroll
    for (int h = 1; h < WH; ++h)
        mx(r[0][0], r[h][0]);
    return r[0][0];
}

// ---------------- Kernel 1: NCHW -> NHWC transpose (proven) ----------------
__global__ void transpose_in_kernel(const float* __restrict__ x) {
    __shared__ float tile[32][33];
    int b  = blockIdx.z;
    int p0 = blockIdx.x * 32;
    int c0 = blockIdx.y * 32;
    int tx = threadIdx.x;
    int ty = threadIdx.y;

    #pragma unroll
    for (int k = 0; k < 4; ++k) {
        int c = c0 + ty + k * 8;
        int p = p0 + tx;
        if (p < HW)
            tile[ty + k * 8][tx] = x[((size_t)b * C_TOT + c) * HW + p];
    }
    __syncthreads();
    #pragma unroll
    for (int k = 0; k < 4; ++k) {
        int p = p0 + ty + k * 8;
        int c = c0 + tx;
        if (p < HW)
            g_xt[((size_t)b * HW + p) * C_TOT + c] = tile[tx][ty + k * 8];
    }
}

// ---------------- Kernel 2: fused bounds + exact-window gather ----------------
__global__ void __launch_bounds__(GTHREADS, 2)
roi_gather_kernel(const float* __restrict__ rois, float* __restrict__ out, int N) {
    __shared__ float s_res[CQ * NBINS];   // flat [c][bin], 12.5 KB
    __shared__ int   s_hs[POOL_H], s_he[POOL_H], s_ws[POOL_W], s_we[POOL_W];
    __shared__ int   s_b;

    int n   = blockIdx.x;
    int qtr = blockIdx.y;                  // 64-channel quarter
    int tid = threadIdx.x;
    int warp = tid >> 5;
    int lane = tid & 31;

    // --- bounds (exact replica of reference arithmetic, incl. div.full) ---
    if (tid < POOL_H + POOL_W + 1) {
        const float* r = rois + n * 5;
        if (tid == POOL_H + POOL_W) {
            s_b = (int)r[0];
        } else {
            bool is_h = (tid < POOL_H);
            int  i    = is_h ? tid : tid - POOL_H;
            float s1  = rintf(__fmul_rn(r[is_h ? 2 : 1], SPATIAL_SCALE));
            float e1  = rintf(__fmul_rn(r[is_h ? 4 : 3], SPATIAL_SCALE));
            float sz  = fmaxf(__fadd_rn(__fsub_rn(e1, s1), 1.0f), 1.0f);
            float bs  = div_full(sz, is_h ? (float)POOL_H : (float)POOL_W);
            float npx = is_h ? (float)HDIM : (float)WDIM;
            float lo = __fadd_rn(floorf(__fmul_rn((float)i, bs)), s1);
            float hi = __fadd_rn(ceilf(__fmul_rn((float)(i + 1), bs)), s1);
            lo = fminf(fmaxf(lo, 0.0f), npx);
            hi = fminf(fmaxf(hi, 0.0f), npx);
            if (is_h) { s_hs[i] = (int)lo; s_he[i] = (int)hi; }
            else      { s_ws[i] = (int)lo; s_we[i] = (int)hi; }
        }
    }
    __syncthreads();

    // --- gather: unit = bin; lane = 2 channels (float2), 64 ch total ---
    const float* xroi = g_xt + (size_t)s_b * (HW * C_TOT) + qtr * CQ + lane * 2;

    for (int bin = warp; bin < NBINS; bin += NWARPS) {   // ~3 units per warp
        int ph = bin / POOL_W;
        int pw = bin - ph * POOL_W;
        int hs = s_hs[ph], he = s_he[ph];
        int ws = s_ws[pw], we = s_we[pw];
        int wh = he - hs, ww = we - ws;

        float2 m;
        if (wh > 0 && ww > 0 && wh <= 4 && ww <= 4) {
            const float* base = xroi + ((size_t)(hs * WDIM) + ws) * C_TOT;
            switch (((wh - 1) << 2) | (ww - 1)) {
                case  0: m = gather_unit<1,1>(base); break;
                case  1: m = gather_unit<1,2>(base); break;
                case  2: m = gather_unit<1,3>(base); break;
                case  3: m = gather_unit<1,4>(base); break;
                case  4: m = gather_unit<2,1>(base); break;
                case  5: m = gather_unit<2,2>(base); break;
                case  6: m = gather_unit<2,3>(base); break;
                case  7: m = gather_unit<2,4>(base); break;
                case  8: m = gather_unit<3,1>(base); break;
                case  9: m = gather_unit<3,2>(base); break;
                case 10: m = gather_unit<3,3>(base); break;
                case 11: m = gather_unit<3,4>(base); break;
                case 12: m = gather_unit<4,1>(base); break;
                case 13: m = gather_unit<4,2>(base); break;
                case 14: m = gather_unit<4,3>(base); break;
                default: m = gather_unit<4,4>(base); break;
            }
        } else if (wh > 0 && ww > 0) {
            // Fallback (never hit with this data shape, kept for safety).
            m = make_float2(NEG_FLT_MAX, NEG_FLT_MAX);
            const float* rowp = xroi + ((size_t)(hs * WDIM) + ws) * C_TOT;
            for (int h = 0; h < wh; ++h) {
                const float* q = rowp;
                for (int w = 0; w < ww; ++w) { mx(m, ld2(q)); q += C_TOT; }
                rowp += ROWSTRIDE;
            }
        } else {
            m = make_float2(0.f, 0.f);
        }

        int c = lane * 2;                            // local channel
        s_res[(c + 0) * NBINS + bin] = m.x;
        s_res[(c + 1) * NBINS + bin] = m.y;
    }
    __syncthreads();

    // --- coalesced staged write: flat 3136 floats = 784 float4 ---
    float* obase = out + (size_t)n * (C_TOT * NBINS) + (size_t)qtr * (CQ * NBINS);
    const float4* src = reinterpret_cast<const float4*>(s_res);
    float4* dst = reinterpret_cast<float4*>(obase);
    {
        int i = tid;
        if (i < (CQ * NBINS) / 4)                    // 784 < 512? no: two rounds
            dst[i] = src[i];
        i += GTHREADS;
        if (i < (CQ * NBINS) / 4)
            dst[i] = src[i];
    }
}

extern "C" void kernel_launch(void* const* d_in, const int* in_sizes, int n_in,
                              void* d_out, int out_size) {
    const float* x    = (const float*)d_in[0];   // [B,256,50,50]
    const float* rois = (const float*)d_in[1];   // [N,5]
    float* out = (float*)d_out;                  // [N,256,7,7]

    const int N = in_sizes[1] / 5;
    const int B = in_sizes[0] / (C_TOT * HW);

    dim3 tgrid((HW + 31) / 32, C_TOT / 32, B);
    dim3 tblock(32, 8);
    transpose_in_kernel<<<tgrid, tblock>>>(x);

    dim3 ggrid(N, C_TOT / CQ);                   // (128, 4) = 512 blocks
    roi_gather_kernel<<<ggrid, GTHREADS>>>(rois, out, N);
}